// round 15
// baseline (speedup 1.0000x reference)
#include <cuda_runtime.h>
#include <cuda_bf16.h>
#include <cuda_fp16.h>
#include <cstdint>
#include <math.h>

#define BATCH 4
#define NN 1024
#define MMM 1024
#define DDD 512
#define EPSI 0.1f
#define MAX_ITER 20
#define THRESH 0.1f
#define LOG_MU_P10 3.06853843f   /* log(1/1024 + 1e-8) + 10 */
#define EXPM10 4.5399930e-05f    /* exp(-10) */
#define NWORK 128                /* worker blocks (4096 rows) */
#define NB 148                   /* slot array size */

// ------------------------- scratch (device globals; no allocs) -------------
__device__ __half g_K [BATCH * NN * MMM];   // 8 MB : K' = exp(10*dot)
__device__ __half g_Kt[BATCH * NN * MMM];   // 8 MB : transposed
__device__ __nv_bfloat16 g_xb[BATCH * NN * DDD];
__device__ __nv_bfloat16 g_yb[BATCH * MMM * DDD];
__device__ float g_a [BATCH * NN];   // u/eps
__device__ float g_EA[BATCH * NN];   // exp(u/eps)
__device__ float g_EB[BATCH * MMM];  // exp(v/eps)
__device__ float g_dupart[NWORK];    // per-block |du| partial sums
__device__ float g_part[BATCH * NN];
__device__ int   g_arr[NB];
__device__ volatile int g_gen;

// ------------------------- prep: warp-per-row normalize + init --------------
__global__ void __launch_bounds__(256) k_prep(const float* __restrict__ x,
                                              const float* __restrict__ y) {
    int warp = threadIdx.x >> 5, lane = threadIdx.x & 31;
    int row = blockIdx.x * 8 + warp;            // 0..8191 (grid = 1024)
    int gid = blockIdx.x * 256 + threadIdx.x;
    if (gid < BATCH * NN) g_a[gid] = 0.0f;
    else if (gid < 2 * BATCH * NN) g_EB[gid - BATCH * NN] = 1.0f;
    if (gid < NB) g_arr[gid] = 0;
    if (gid == 0) g_gen = 0;

    const float* p;
    __nv_bfloat16* q;
    if (row < BATCH * NN) { p = x + (size_t)row * DDD; q = g_xb + (size_t)row * DDD; }
    else { p = y + (size_t)(row - BATCH * NN) * DDD; q = g_yb + (size_t)(row - BATCH * NN) * DDD; }

    float4 v[4];
    float s = 0.0f;
    #pragma unroll
    for (int j = 0; j < 4; j++) {
        v[j] = *(const float4*)(p + (j * 32 + lane) * 4);
        s += v[j].x * v[j].x + v[j].y * v[j].y + v[j].z * v[j].z + v[j].w * v[j].w;
    }
    #pragma unroll
    for (int o = 16; o; o >>= 1) s += __shfl_xor_sync(0xffffffffu, s, o);
    float iv = (s > 0.0f) ? rsqrtf(s) : 0.0f;
    #pragma unroll
    for (int j = 0; j < 4; j++) {
        __nv_bfloat162 h0 = __floats2bfloat162_rn(v[j].x * iv, v[j].y * iv);
        __nv_bfloat162 h1 = __floats2bfloat162_rn(v[j].z * iv, v[j].w * iv);
        uint2 pk = make_uint2(*(uint32_t*)&h0, *(uint32_t*)&h1);
        *(uint2*)(q + (j * 32 + lane) * 4) = pk;
    }
}

// ------------------------- bf16 mma GEMM -> K', K't (R12 version) -----------
__device__ __forceinline__ void mma_bf16(float* c, const uint32_t* a, const uint32_t* b) {
    asm volatile(
        "mma.sync.aligned.m16n8k16.row.col.f32.bf16.bf16.f32 "
        "{%0,%1,%2,%3}, {%4,%5,%6,%7}, {%8,%9}, {%0,%1,%2,%3};\n"
        : "+f"(c[0]), "+f"(c[1]), "+f"(c[2]), "+f"(c[3])
        : "r"(a[0]), "r"(a[1]), "r"(a[2]), "r"(a[3]), "r"(b[0]), "r"(b[1]));
}

__device__ __forceinline__ void ldmx4(uint32_t* r, uint32_t addr) {
    asm volatile("ldmatrix.sync.aligned.m8n8.x4.shared.b16 {%0,%1,%2,%3}, [%4];\n"
        : "=r"(r[0]), "=r"(r[1]), "=r"(r[2]), "=r"(r[3]) : "r"(addr));
}

__device__ __forceinline__ void cpa16(void* s, const void* g) {
    asm volatile("cp.async.cg.shared.global [%0], [%1], 16;\n"
        :: "r"((uint32_t)__cvta_generic_to_shared(s)), "l"(g));
}
__device__ __forceinline__ void cpa_commit() {
    asm volatile("cp.async.commit_group;\n");
}
template <int N>
__device__ __forceinline__ void cpa_wait() {
    asm volatile("cp.async.wait_group %0;\n" :: "n"(N));
}

#define SSTRIDE 40
#define STRB    80
#define AS_BYTES (256 * STRB)
#define SM_TOTAL (2 * AS_BYTES)

__global__ void __launch_bounds__(256, 2) k_gemm() {
    __shared__ __align__(16) char sraw[SM_TOTAL];
    __nv_bfloat16 (*As)[SSTRIDE] = (__nv_bfloat16(*)[SSTRIDE])sraw;
    __nv_bfloat16 (*Bs)[SSTRIDE] = (__nv_bfloat16(*)[SSTRIDE])(sraw + AS_BYTES);
    __half (*Ts)[136] = (__half(*)[136])sraw;

    int b = blockIdx.z;
    const __nv_bfloat16* A  = g_xb + ((size_t)b * NN  + blockIdx.x * 128) * DDD;
    const __nv_bfloat16* Bp = g_yb + ((size_t)b * MMM + blockIdx.y * 128) * DDD;

    int tid = threadIdx.x;
    int warp = tid >> 5;
    int lane = tid & 31;
    int wm = (warp & 1) * 64;
    int wn = (warp >> 1) * 32;
    int g  = lane >> 2;
    int tq = lane & 3;

    uint32_t sbase = (uint32_t)__cvta_generic_to_shared(sraw);
    uint32_t aL = sbase + (uint32_t)(wm + (lane & 15)) * STRB + (lane >> 4) * 16;
    uint32_t bL = sbase + AS_BYTES
                + (uint32_t)(wn + ((lane >> 4) & 1) * 8 + (lane & 7)) * STRB
                + ((lane >> 3) & 1) * 16;

    int c0 = tid * 2;
    int r0_ = c0 >> 2, q0 = c0 & 3;
    int c1 = c0 + 1;
    int r1_ = c1 >> 2, q1 = c1 & 3;

    float acc[4][4][4];
    #pragma unroll
    for (int mt = 0; mt < 4; mt++)
        #pragma unroll
        for (int nt = 0; nt < 4; nt++)
            #pragma unroll
            for (int i = 0; i < 4; i++) acc[mt][nt][i] = 0.0f;

    #pragma unroll
    for (int st = 0; st < 2; st++) {
        int ko = st * 32;
        cpa16(&As[st * 128 + r0_][q0 * 8], A  + (size_t)r0_ * DDD + ko + q0 * 8);
        cpa16(&As[st * 128 + r1_][q1 * 8], A  + (size_t)r1_ * DDD + ko + q1 * 8);
        cpa16(&Bs[st * 128 + r0_][q0 * 8], Bp + (size_t)r0_ * DDD + ko + q0 * 8);
        cpa16(&Bs[st * 128 + r1_][q1 * 8], Bp + (size_t)r1_ * DDD + ko + q1 * 8);
        cpa_commit();
    }

    for (int kt = 0; kt < DDD / 32; kt++) {
        cpa_wait<1>();
        __syncthreads();
        uint32_t stoff = (uint32_t)(kt & 1) * (128 * STRB);

        #pragma unroll
        for (int ks = 0; ks < 2; ks++) {
            uint32_t kb = ks * 32;
            uint32_t af[4][4];
            #pragma unroll
            for (int mt = 0; mt < 4; mt++)
                ldmx4(af[mt], aL + stoff + (uint32_t)mt * (16 * STRB) + kb);
            uint32_t b4[2][4];
            #pragma unroll
            for (int ntp = 0; ntp < 2; ntp++)
                ldmx4(b4[ntp], bL + stoff + (uint32_t)ntp * (16 * STRB) + kb);
            #pragma unroll
            for (int mt = 0; mt < 4; mt++)
                #pragma unroll
                for (int nt = 0; nt < 4; nt++)
                    mma_bf16(acc[mt][nt], af[mt], &b4[nt >> 1][(nt & 1) * 2]);
        }
        __syncthreads();
        int st = (kt & 1) * 128;
        if (kt + 2 < DDD / 32) {
            int ko = (kt + 2) * 32;
            cpa16(&As[st + r0_][q0 * 8], A  + (size_t)r0_ * DDD + ko + q0 * 8);
            cpa16(&As[st + r1_][q1 * 8], A  + (size_t)r1_ * DDD + ko + q1 * 8);
            cpa16(&Bs[st + r0_][q0 * 8], Bp + (size_t)r0_ * DDD + ko + q0 * 8);
            cpa16(&Bs[st + r1_][q1 * 8], Bp + (size_t)r1_ * DDD + ko + q1 * 8);
        }
        cpa_commit();
    }
    cpa_wait<0>();

    size_t cb = (size_t)b * NN * MMM;
    __half* Kp  = g_K  + cb;
    __half* Ktp = g_Kt + cb;

    for (int hp = 0; hp < 2; hp++) {
        __syncthreads();
        if ((warp & 1) == hp) {
            #pragma unroll
            for (int mt = 0; mt < 4; mt++) {
                #pragma unroll
                for (int nt = 0; nt < 4; nt++) {
                    int lr0 = mt * 16 + g;
                    int cc  = wn + nt * 8 + 2 * tq;
                    Ts[lr0][cc]        = __float2half(__expf(acc[mt][nt][0] * 10.0f));
                    Ts[lr0][cc + 1]    = __float2half(__expf(acc[mt][nt][1] * 10.0f));
                    Ts[lr0 + 8][cc]    = __float2half(__expf(acc[mt][nt][2] * 10.0f));
                    Ts[lr0 + 8][cc+1]  = __float2half(__expf(acc[mt][nt][3] * 10.0f));
                }
            }
        }
        __syncthreads();
        int roff = hp * 64;
        #pragma unroll
        for (int id = tid; id < 1024; id += 256) {
            int r = id >> 4, ch = id & 15;
            uint4 v = *(uint4*)&Ts[r][ch * 8];
            *(uint4*)(Kp + (size_t)(blockIdx.x * 128 + roff + r) * MMM
                          + blockIdx.y * 128 + ch * 8) = v;
        }
        #pragma unroll
        for (int id = tid; id < 1024; id += 256) {
            int m = id >> 3, ch = id & 7;
            __align__(16) __half tmp[8];
            #pragma unroll
            for (int j = 0; j < 8; j++) tmp[j] = Ts[ch * 8 + j][m];
            *(uint4*)(Ktp + (size_t)(blockIdx.y * 128 + m) * NN
                           + blockIdx.x * 128 + roff + ch * 8) = *(uint4*)tmp;
        }
    }
}

// --------- symmetric all-poll grid barrier: no mediator round-trip ----------
__device__ __forceinline__ void gridbar(int bid, int tid, int& gen) {
    __syncthreads();
    gen++;
    if (tid == 0) {
        __threadfence();
        ((volatile int*)g_arr)[bid] = gen;
    }
    if (tid < NWORK) {
        while (((volatile int*)g_arr)[tid] < gen) { }
    }
    __syncthreads();
    __threadfence();
}

// ------------------------- persistent Sinkhorn loop + cost ------------------
__global__ void __launch_bounds__(1024, 1) k_loop(const float* __restrict__ nu,
                                                  float* __restrict__ out) {
    __shared__ float sE[NN];       // 4 KB: this block's batch slice of EA/EB
    __shared__ float sred[32];
    __shared__ int   sdone;
    int tid = threadIdx.x, bid = blockIdx.x;
    int warp = tid >> 5, lane = tid & 31;
    int gw = bid * 32 + warp;          // global row index, 0..4095
    int gen = 0;

    const __half* Krow  = g_K  + ((size_t)gw << 10);
    const __half* Ktrow = g_Kt + ((size_t)gw << 10);
    const int b0 = (bid * 32) >> 10;   // batch of this block

    for (int it = 0; it < MAX_ITER; it++) {
        // ---- row pass: a_new = LOG_MU_P10 - ln(K' @ EB) ----
        sE[tid] = __ldcg(&g_EB[(b0 << 10) + tid]);
        __syncthreads();
        {
            float s = 0.0f;
            #pragma unroll
            for (int j = 0; j < 8; j++) {
                int m = (j * 32 + lane) * 4;
                uint2 kv = *(const uint2*)(Krow + m);
                float4 e = *(const float4*)(sE + m);
                float2 f0 = __half22float2(*(__half2*)&kv.x);
                float2 f1 = __half22float2(*(__half2*)&kv.y);
                s += f0.x * e.x + f0.y * e.y + f1.x * e.z + f1.y * e.w;
            }
            #pragma unroll
            for (int o = 16; o; o >>= 1) s += __shfl_xor_sync(0xffffffffu, s, o);
            float a_new = LOG_MU_P10 - __logf(s);
            float du = fabsf(a_new - g_a[gw]) * EPSI;
            if (lane == 0) {
                g_a[gw]  = a_new;
                g_EA[gw] = __expf(a_new);
                sred[warp] = du;
            }
        }
        __syncthreads();
        if (warp == 0) {
            float d = sred[lane];
            #pragma unroll
            for (int o = 16; o; o >>= 1) d += __shfl_xor_sync(0xffffffffu, d, o);
            if (lane == 0) g_dupart[bid] = d;
        }
        gridbar(bid, tid, gen);            // barrier A

        // issue du-partial loads early; latency hidden by col pass
        float mydu = (tid < NWORK) ? __ldcg(&g_dupart[tid]) : 0.0f;

        // ---- col pass: b_new = log(nu)+10 - ln(K't @ EA) ----
        sE[tid] = __ldcg(&g_EA[(b0 << 10) + tid]);
        __syncthreads();
        {
            float s = 0.0f;
            #pragma unroll
            for (int j = 0; j < 8; j++) {
                int n = (j * 32 + lane) * 4;
                uint2 kv = *(const uint2*)(Ktrow + n);
                float4 e = *(const float4*)(sE + n);
                float2 f0 = __half22float2(*(__half2*)&kv.x);
                float2 f1 = __half22float2(*(__half2*)&kv.y);
                s += f0.x * e.x + f0.y * e.y + f1.x * e.z + f1.y * e.w;
            }
            #pragma unroll
            for (int o = 16; o; o >>= 1) s += __shfl_xor_sync(0xffffffffu, s, o);
            if (lane == 0)
                g_EB[gw] = __expf(__logf(nu[gw] + 1e-8f) + 10.0f - __logf(s));
        }

        // ---- distributed convergence check (identical in every block) ----
        if (warp < 4) {
            #pragma unroll
            for (int o = 16; o; o >>= 1) mydu += __shfl_xor_sync(0xffffffffu, mydu, o);
            if (lane == 0) sred[warp] = mydu;
        }
        __syncthreads();
        if (tid == 0) {
            float tot = sred[0] + sred[1] + sred[2] + sred[3];
            sdone = (tot * (1.0f / BATCH) < THRESH) ? 1 : 0;
        }
        gridbar(bid, tid, gen);            // barrier B
        if (sdone) break;
    }

    // ---- cost: part[n] = EA[n] * sum_m K*(1 - 0.1*ln K)*EB[m] ----
    sE[tid] = __ldcg(&g_EB[(b0 << 10) + tid]);
    __syncthreads();
    {
        float s = 0.0f;
        #pragma unroll
        for (int j = 0; j < 8; j++) {
            int m = (j * 32 + lane) * 4;
            uint2 kv = *(const uint2*)(Krow + m);
            float4 e = *(const float4*)(sE + m);
            float2 f0 = __half22float2(*(__half2*)&kv.x);
            float2 f1 = __half22float2(*(__half2*)&kv.y);
            s += f0.x * (1.0f - 0.1f * __logf(f0.x)) * e.x;
            s += f0.y * (1.0f - 0.1f * __logf(f0.y)) * e.y;
            s += f1.x * (1.0f - 0.1f * __logf(f1.x)) * e.z;
            s += f1.y * (1.0f - 0.1f * __logf(f1.y)) * e.w;
        }
        #pragma unroll
        for (int o = 16; o; o >>= 1) s += __shfl_xor_sync(0xffffffffu, s, o);
        if (lane == 0) g_part[gw] = s * __ldcg(&g_EA[gw]);
    }
    gridbar(bid, tid, gen);                // barrier C

    // ---- block 0: deterministic per-batch reduction -> out ----
    if (bid == 0) {
        int b = tid >> 8;
        int t = tid & 255;
        float s = 0.0f;
        for (int i = t; i < NN; i += 256) s += __ldcg(&g_part[(b << 10) + i]);
        #pragma unroll
        for (int o = 16; o; o >>= 1) s += __shfl_xor_sync(0xffffffffu, s, o);
        if (lane == 0) sred[warp] = s;
        __syncthreads();
        if (tid < BATCH) {
            float tot = 0.0f;
            #pragma unroll
            for (int i = 0; i < 8; i++) tot += sred[tid * 8 + i];
            out[tid] = tot * EXPM10;
        }
    }
}

// ------------------------- launcher ----------------------------------------
extern "C" void kernel_launch(void* const* d_in, const int* in_sizes, int n_in,
                              void* d_out, int out_size) {
    (void)in_sizes; (void)n_in; (void)out_size;
    const float* x  = (const float*)d_in[0];
    const float* y  = (const float*)d_in[1];
    const float* nu = (const float*)d_in[2];
    float* out = (float*)d_out;

    k_prep<<<1024, 256>>>(x, y);

    dim3 gg(NN / 128, MMM / 128, BATCH);
    k_gemm<<<gg, 256>>>();

    k_loop<<<NWORK, 1024>>>(nu, out);
}

// round 16
// speedup vs baseline: 1.5068x; 1.5068x over previous
#include <cuda_runtime.h>
#include <cuda_bf16.h>
#include <cuda_fp16.h>
#include <cstdint>
#include <math.h>

#define BATCH 4
#define NN 1024
#define MMM 1024
#define DDD 512
#define EPSI 0.1f
#define MAX_ITER 20
#define THRESH 0.1f
#define LOG_MU_P10 3.06853843f   /* log(1/1024 + 1e-8) + 10 */
#define EXPM10 4.5399930e-05f    /* exp(-10) */
#define NWORK 128                /* worker blocks (4096 rows) */
#define NB 148                   /* slot array size */

// ------------------------- scratch (device globals; no allocs) -------------
__device__ __half g_K [BATCH * NN * MMM];   // 8 MB : K' = exp(10*dot)
__device__ __half g_Kt[BATCH * NN * MMM];   // 8 MB : transposed
__device__ __nv_bfloat16 g_xb[BATCH * NN * DDD];
__device__ __nv_bfloat16 g_yb[BATCH * MMM * DDD];
__device__ float g_a [BATCH * NN];   // u/eps
__device__ float g_EA[BATCH * NN];   // exp(u/eps)
__device__ float g_EB[BATCH * MMM];  // exp(v/eps)
__device__ float g_dupart[NWORK];    // per-block |du| partial sums
__device__ float g_part[BATCH * NN];
__device__ int   g_arr[NB];
__device__ volatile int g_gen;

// ------------------------- prep: warp-per-row normalize + init --------------
__global__ void __launch_bounds__(256) k_prep(const float* __restrict__ x,
                                              const float* __restrict__ y) {
    int warp = threadIdx.x >> 5, lane = threadIdx.x & 31;
    int row = blockIdx.x * 8 + warp;            // 0..8191 (grid = 1024)
    int gid = blockIdx.x * 256 + threadIdx.x;
    if (gid < BATCH * NN) g_a[gid] = 0.0f;
    else if (gid < 2 * BATCH * NN) g_EB[gid - BATCH * NN] = 1.0f;
    if (gid < NB) g_arr[gid] = 0;
    if (gid == 0) g_gen = 0;

    const float* p;
    __nv_bfloat16* q;
    if (row < BATCH * NN) { p = x + (size_t)row * DDD; q = g_xb + (size_t)row * DDD; }
    else { p = y + (size_t)(row - BATCH * NN) * DDD; q = g_yb + (size_t)(row - BATCH * NN) * DDD; }

    float4 v[4];
    float s = 0.0f;
    #pragma unroll
    for (int j = 0; j < 4; j++) {
        v[j] = *(const float4*)(p + (j * 32 + lane) * 4);
        s += v[j].x * v[j].x + v[j].y * v[j].y + v[j].z * v[j].z + v[j].w * v[j].w;
    }
    #pragma unroll
    for (int o = 16; o; o >>= 1) s += __shfl_xor_sync(0xffffffffu, s, o);
    float iv = (s > 0.0f) ? rsqrtf(s) : 0.0f;
    #pragma unroll
    for (int j = 0; j < 4; j++) {
        __nv_bfloat162 h0 = __floats2bfloat162_rn(v[j].x * iv, v[j].y * iv);
        __nv_bfloat162 h1 = __floats2bfloat162_rn(v[j].z * iv, v[j].w * iv);
        uint2 pk = make_uint2(*(uint32_t*)&h0, *(uint32_t*)&h1);
        *(uint2*)(q + (j * 32 + lane) * 4) = pk;
    }
}

// ------------------------- bf16 mma GEMM -> K', K't (R12 version) -----------
__device__ __forceinline__ void mma_bf16(float* c, const uint32_t* a, const uint32_t* b) {
    asm volatile(
        "mma.sync.aligned.m16n8k16.row.col.f32.bf16.bf16.f32 "
        "{%0,%1,%2,%3}, {%4,%5,%6,%7}, {%8,%9}, {%0,%1,%2,%3};\n"
        : "+f"(c[0]), "+f"(c[1]), "+f"(c[2]), "+f"(c[3])
        : "r"(a[0]), "r"(a[1]), "r"(a[2]), "r"(a[3]), "r"(b[0]), "r"(b[1]));
}

__device__ __forceinline__ void ldmx4(uint32_t* r, uint32_t addr) {
    asm volatile("ldmatrix.sync.aligned.m8n8.x4.shared.b16 {%0,%1,%2,%3}, [%4];\n"
        : "=r"(r[0]), "=r"(r[1]), "=r"(r[2]), "=r"(r[3]) : "r"(addr));
}

__device__ __forceinline__ void cpa16(void* s, const void* g) {
    asm volatile("cp.async.cg.shared.global [%0], [%1], 16;\n"
        :: "r"((uint32_t)__cvta_generic_to_shared(s)), "l"(g));
}
__device__ __forceinline__ void cpa_commit() {
    asm volatile("cp.async.commit_group;\n");
}
template <int N>
__device__ __forceinline__ void cpa_wait() {
    asm volatile("cp.async.wait_group %0;\n" :: "n"(N));
}

#define SSTRIDE 40
#define STRB    80
#define AS_BYTES (256 * STRB)
#define SM_TOTAL (2 * AS_BYTES)

__global__ void __launch_bounds__(256, 2) k_gemm() {
    __shared__ __align__(16) char sraw[SM_TOTAL];
    __nv_bfloat16 (*As)[SSTRIDE] = (__nv_bfloat16(*)[SSTRIDE])sraw;
    __nv_bfloat16 (*Bs)[SSTRIDE] = (__nv_bfloat16(*)[SSTRIDE])(sraw + AS_BYTES);
    __half (*Ts)[136] = (__half(*)[136])sraw;

    int b = blockIdx.z;
    const __nv_bfloat16* A  = g_xb + ((size_t)b * NN  + blockIdx.x * 128) * DDD;
    const __nv_bfloat16* Bp = g_yb + ((size_t)b * MMM + blockIdx.y * 128) * DDD;

    int tid = threadIdx.x;
    int warp = tid >> 5;
    int lane = tid & 31;
    int wm = (warp & 1) * 64;
    int wn = (warp >> 1) * 32;
    int g  = lane >> 2;
    int tq = lane & 3;

    uint32_t sbase = (uint32_t)__cvta_generic_to_shared(sraw);
    uint32_t aL = sbase + (uint32_t)(wm + (lane & 15)) * STRB + (lane >> 4) * 16;
    uint32_t bL = sbase + AS_BYTES
                + (uint32_t)(wn + ((lane >> 4) & 1) * 8 + (lane & 7)) * STRB
                + ((lane >> 3) & 1) * 16;

    int c0 = tid * 2;
    int r0_ = c0 >> 2, q0 = c0 & 3;
    int c1 = c0 + 1;
    int r1_ = c1 >> 2, q1 = c1 & 3;

    float acc[4][4][4];
    #pragma unroll
    for (int mt = 0; mt < 4; mt++)
        #pragma unroll
        for (int nt = 0; nt < 4; nt++)
            #pragma unroll
            for (int i = 0; i < 4; i++) acc[mt][nt][i] = 0.0f;

    #pragma unroll
    for (int st = 0; st < 2; st++) {
        int ko = st * 32;
        cpa16(&As[st * 128 + r0_][q0 * 8], A  + (size_t)r0_ * DDD + ko + q0 * 8);
        cpa16(&As[st * 128 + r1_][q1 * 8], A  + (size_t)r1_ * DDD + ko + q1 * 8);
        cpa16(&Bs[st * 128 + r0_][q0 * 8], Bp + (size_t)r0_ * DDD + ko + q0 * 8);
        cpa16(&Bs[st * 128 + r1_][q1 * 8], Bp + (size_t)r1_ * DDD + ko + q1 * 8);
        cpa_commit();
    }

    for (int kt = 0; kt < DDD / 32; kt++) {
        cpa_wait<1>();
        __syncthreads();
        uint32_t stoff = (uint32_t)(kt & 1) * (128 * STRB);

        #pragma unroll
        for (int ks = 0; ks < 2; ks++) {
            uint32_t kb = ks * 32;
            uint32_t af[4][4];
            #pragma unroll
            for (int mt = 0; mt < 4; mt++)
                ldmx4(af[mt], aL + stoff + (uint32_t)mt * (16 * STRB) + kb);
            uint32_t b4[2][4];
            #pragma unroll
            for (int ntp = 0; ntp < 2; ntp++)
                ldmx4(b4[ntp], bL + stoff + (uint32_t)ntp * (16 * STRB) + kb);
            #pragma unroll
            for (int mt = 0; mt < 4; mt++)
                #pragma unroll
                for (int nt = 0; nt < 4; nt++)
                    mma_bf16(acc[mt][nt], af[mt], &b4[nt >> 1][(nt & 1) * 2]);
        }
        __syncthreads();
        int st = (kt & 1) * 128;
        if (kt + 2 < DDD / 32) {
            int ko = (kt + 2) * 32;
            cpa16(&As[st + r0_][q0 * 8], A  + (size_t)r0_ * DDD + ko + q0 * 8);
            cpa16(&As[st + r1_][q1 * 8], A  + (size_t)r1_ * DDD + ko + q1 * 8);
            cpa16(&Bs[st + r0_][q0 * 8], Bp + (size_t)r0_ * DDD + ko + q0 * 8);
            cpa16(&Bs[st + r1_][q1 * 8], Bp + (size_t)r1_ * DDD + ko + q1 * 8);
        }
        cpa_commit();
    }
    cpa_wait<0>();

    size_t cb = (size_t)b * NN * MMM;
    __half* Kp  = g_K  + cb;
    __half* Ktp = g_Kt + cb;

    for (int hp = 0; hp < 2; hp++) {
        __syncthreads();
        if ((warp & 1) == hp) {
            #pragma unroll
            for (int mt = 0; mt < 4; mt++) {
                #pragma unroll
                for (int nt = 0; nt < 4; nt++) {
                    int lr0 = mt * 16 + g;
                    int cc  = wn + nt * 8 + 2 * tq;
                    Ts[lr0][cc]        = __float2half(__expf(acc[mt][nt][0] * 10.0f));
                    Ts[lr0][cc + 1]    = __float2half(__expf(acc[mt][nt][1] * 10.0f));
                    Ts[lr0 + 8][cc]    = __float2half(__expf(acc[mt][nt][2] * 10.0f));
                    Ts[lr0 + 8][cc+1]  = __float2half(__expf(acc[mt][nt][3] * 10.0f));
                }
            }
        }
        __syncthreads();
        int roff = hp * 64;
        #pragma unroll
        for (int id = tid; id < 1024; id += 256) {
            int r = id >> 4, ch = id & 15;
            uint4 v = *(uint4*)&Ts[r][ch * 8];
            *(uint4*)(Kp + (size_t)(blockIdx.x * 128 + roff + r) * MMM
                          + blockIdx.y * 128 + ch * 8) = v;
        }
        #pragma unroll
        for (int id = tid; id < 1024; id += 256) {
            int m = id >> 3, ch = id & 7;
            __align__(16) __half tmp[8];
            #pragma unroll
            for (int j = 0; j < 8; j++) tmp[j] = Ts[ch * 8 + j][m];
            *(uint4*)(Ktp + (size_t)(blockIdx.y * 128 + m) * NN
                           + blockIdx.x * 128 + roff + ch * 8) = *(uint4*)tmp;
        }
    }
}

// ---- mediated grid barrier, warp-0-only mediator (slim release path) -------
__device__ __forceinline__ void gridbar(int bid, int tid, int& gen) {
    __syncthreads();
    gen++;
    if (bid == 0) {
        if (tid < 32) {
            // lane l polls slots l, l+32, l+64, l+96 (slot 0 = self, skip)
            volatile int* a = (volatile int*)g_arr;
            int p0 = (tid == 0) ? 1 : 0;   // lane0 skips its own slot 0
            for (;;) {
                int v0 = p0 ? gen : a[tid];
                int v1 = a[tid + 32];
                int v2 = a[tid + 64];
                int v3 = a[tid + 96];
                if (v0 >= gen && v1 >= gen && v2 >= gen && v3 >= gen) break;
            }
            __syncwarp();
            if (tid == 0) { __threadfence(); g_gen = gen; }
        }
        __syncthreads();
    } else {
        if (tid == 0) {
            __threadfence();
            ((volatile int*)g_arr)[bid] = gen;
            while (g_gen < gen) { }
        }
        __syncthreads();
    }
    __threadfence();
}

// ------------------------- persistent Sinkhorn loop + cost ------------------
__global__ void __launch_bounds__(1024, 1) k_loop(const float* __restrict__ nu,
                                                  float* __restrict__ out) {
    __shared__ float sE[NN];       // 4 KB: this block's batch slice of EA/EB
    __shared__ float sred[32];
    __shared__ int   sdone;
    int tid = threadIdx.x, bid = blockIdx.x;
    int warp = tid >> 5, lane = tid & 31;
    int gw = bid * 32 + warp;          // global row index, 0..4095
    int gen = 0;

    const __half* Krow  = g_K  + ((size_t)gw << 10);
    const __half* Ktrow = g_Kt + ((size_t)gw << 10);
    const int b0 = (bid * 32) >> 10;   // batch of this block

    for (int it = 0; it < MAX_ITER; it++) {
        // ---- row pass: a_new = LOG_MU_P10 - ln(K' @ EB) ----
        sE[tid] = __ldcg(&g_EB[(b0 << 10) + tid]);
        __syncthreads();
        {
            float s = 0.0f;
            #pragma unroll
            for (int j = 0; j < 8; j++) {
                int m = (j * 32 + lane) * 4;
                uint2 kv = *(const uint2*)(Krow + m);
                float4 e = *(const float4*)(sE + m);
                float2 f0 = __half22float2(*(__half2*)&kv.x);
                float2 f1 = __half22float2(*(__half2*)&kv.y);
                s += f0.x * e.x + f0.y * e.y + f1.x * e.z + f1.y * e.w;
            }
            #pragma unroll
            for (int o = 16; o; o >>= 1) s += __shfl_xor_sync(0xffffffffu, s, o);
            float a_new = LOG_MU_P10 - __logf(s);
            float du = fabsf(a_new - g_a[gw]) * EPSI;
            if (lane == 0) {
                g_a[gw]  = a_new;
                g_EA[gw] = __expf(a_new);
                sred[warp] = du;
            }
        }
        __syncthreads();
        if (warp == 0) {
            float d = sred[lane];
            #pragma unroll
            for (int o = 16; o; o >>= 1) d += __shfl_xor_sync(0xffffffffu, d, o);
            if (lane == 0) g_dupart[bid] = d;
        }
        gridbar(bid, tid, gen);            // barrier A

        // issue du-partial loads early; latency hidden by col pass
        float mydu = (tid < NWORK) ? __ldcg(&g_dupart[tid]) : 0.0f;

        // ---- col pass: b_new = log(nu)+10 - ln(K't @ EA) ----
        sE[tid] = __ldcg(&g_EA[(b0 << 10) + tid]);
        __syncthreads();
        {
            float s = 0.0f;
            #pragma unroll
            for (int j = 0; j < 8; j++) {
                int n = (j * 32 + lane) * 4;
                uint2 kv = *(const uint2*)(Ktrow + n);
                float4 e = *(const float4*)(sE + n);
                float2 f0 = __half22float2(*(__half2*)&kv.x);
                float2 f1 = __half22float2(*(__half2*)&kv.y);
                s += f0.x * e.x + f0.y * e.y + f1.x * e.z + f1.y * e.w;
            }
            #pragma unroll
            for (int o = 16; o; o >>= 1) s += __shfl_xor_sync(0xffffffffu, s, o);
            if (lane == 0)
                g_EB[gw] = __expf(__logf(nu[gw] + 1e-8f) + 10.0f - __logf(s));
        }

        // ---- distributed convergence check (identical in every block) ----
        if (warp < 4) {
            #pragma unroll
            for (int o = 16; o; o >>= 1) mydu += __shfl_xor_sync(0xffffffffu, mydu, o);
            if (lane == 0) sred[warp] = mydu;
        }
        __syncthreads();
        if (tid == 0) {
            float tot = sred[0] + sred[1] + sred[2] + sred[3];
            sdone = (tot * (1.0f / BATCH) < THRESH) ? 1 : 0;
        }
        gridbar(bid, tid, gen);            // barrier B
        if (sdone) break;
    }

    // ---- cost: part[n] = EA[n] * sum_m K*(1 - 0.1*ln K)*EB[m] ----
    sE[tid] = __ldcg(&g_EB[(b0 << 10) + tid]);
    __syncthreads();
    {
        float s = 0.0f;
        #pragma unroll
        for (int j = 0; j < 8; j++) {
            int m = (j * 32 + lane) * 4;
            uint2 kv = *(const uint2*)(Krow + m);
            float4 e = *(const float4*)(sE + m);
            float2 f0 = __half22float2(*(__half2*)&kv.x);
            float2 f1 = __half22float2(*(__half2*)&kv.y);
            s += f0.x * (1.0f - 0.1f * __logf(f0.x)) * e.x;
            s += f0.y * (1.0f - 0.1f * __logf(f0.y)) * e.y;
            s += f1.x * (1.0f - 0.1f * __logf(f1.x)) * e.z;
            s += f1.y * (1.0f - 0.1f * __logf(f1.y)) * e.w;
        }
        #pragma unroll
        for (int o = 16; o; o >>= 1) s += __shfl_xor_sync(0xffffffffu, s, o);
        if (lane == 0) g_part[gw] = s * __ldcg(&g_EA[gw]);
    }
    gridbar(bid, tid, gen);                // barrier C

    // ---- block 0: deterministic per-batch reduction -> out ----
    if (bid == 0) {
        int b = tid >> 8;
        int t = tid & 255;
        float s = 0.0f;
        for (int i = t; i < NN; i += 256) s += __ldcg(&g_part[(b << 10) + i]);
        #pragma unroll
        for (int o = 16; o; o >>= 1) s += __shfl_xor_sync(0xffffffffu, s, o);
        if (lane == 0) sred[warp] = s;
        __syncthreads();
        if (tid < BATCH) {
            float tot = 0.0f;
            #pragma unroll
            for (int i = 0; i < 8; i++) tot += sred[tid * 8 + i];
            out[tid] = tot * EXPM10;
        }
    }
}

// ------------------------- launcher ----------------------------------------
extern "C" void kernel_launch(void* const* d_in, const int* in_sizes, int n_in,
                              void* d_out, int out_size) {
    (void)in_sizes; (void)n_in; (void)out_size;
    const float* x  = (const float*)d_in[0];
    const float* y  = (const float*)d_in[1];
    const float* nu = (const float*)d_in[2];
    float* out = (float*)d_out;

    k_prep<<<1024, 256>>>(x, y);

    dim3 gg(NN / 128, MMM / 128, BATCH);
    k_gemm<<<gg, 256>>>();

    k_loop<<<NWORK, 1024>>>(nu, out);
}